// round 15
// baseline (speedup 1.0000x reference)
#include <cuda_runtime.h>

// EarthMoverDistance auction (B=8, N=M=2048).
// Round-14 structure (SPLIT=8, 4 rows/warp replicated, warp-pair column halves,
// linear d2, float2 payload, power trick, PDL) + SMEM STAGING of the streamed
// float4 point array: LDS broadcast dedups the 4-way lane replication that L1
// refuses to dedup (measured: LDG wavefronts count every lane's bytes).

#define NB 8
#define NP 2048
#define TPB 256
#define RPB 16                   // rows per block
#define BPB (NP / RPB)           // 128 blocks per batch
#define GRID (NB * BPB)          // 1024 blocks
#define HC (NP / 2)              // columns per warp (half range)
#define FULL 0xFFFFFFFFu
#define SKIP_T  (-125.0f)
#define SKIP4_T (-31.25f)

// Static scratch (no allocations)
__device__ float4 g_P[NB * NP];      // set1 {x,y,z,|p|^2}
__device__ float4 g_Q[NB * NP];      // set2 {x,y,z,|q|^2}
__device__ float2 g_W[NB * NP];      // {rcR, remainR}
__device__ float  g_rs[NB * NP];     // rowscale
__device__ float  g_remainL[NB * NP];
__device__ float  g_cost[NB];

__device__ __forceinline__ float ex2a(float x) {
    float r; asm("ex2.approx.f32 %0, %1;" : "=f"(r) : "f"(x)); return r;
}
__device__ __forceinline__ float sqrta(float x) {
    float r; asm("sqrt.approx.f32 %0, %1;" : "=f"(r) : "f"(x)); return r;
}
__device__ __forceinline__ float wred8(float v) {
    v += __shfl_xor_sync(FULL, v, 1);
    v += __shfl_xor_sync(FULL, v, 2);
    v += __shfl_xor_sync(FULL, v, 4);
    return v;
}
__device__ __forceinline__ void pdl_wait() {
    cudaGridDependencySynchronize();
}

__global__ void emd_init(const float* __restrict__ x1,
                         const float* __restrict__ x2) {
    int i = blockIdx.x * blockDim.x + threadIdx.x;
    pdl_wait();
    if (i < NB) g_cost[i] = 0.0f;
    if (i < NB * NP) {
        float a = x1[3*i], b = x1[3*i+1], c = x1[3*i+2];
        g_P[i] = make_float4(a, b, c, fmaf(a, a, fmaf(b, b, c * c)));
        float d = x2[3*i], e = x2[3*i+1], f = x2[3*i+2];
        g_Q[i] = make_float4(d, e, f, fmaf(d, d, fmaf(e, e, f * f)));
        g_W[i] = make_float2(0.0f, 1.0f);   // {rcR, remainR=multiR}
        g_rs[i] = 0.0f;
        g_remainL[i] = 1.0f;                // multiL
    }
}

// ---- Pass A (level 0 only): rowscale = remainL / (rowsum + 1e-9) ----
__global__ __launch_bounds__(TPB) void emd_passA(float c) {
    __shared__ float4 sQ[NP];            // 32KB staged stream
    __shared__ float sA[RPB][2];
    int tid = threadIdx.x, lane = tid & 31, w = tid >> 5;
    int half = w & 1, sub = lane & 7;
    int rloc = ((w >> 1) << 2) + (lane >> 3);     // 0..15
    int b = blockIdx.x >> 7;
    int r0 = (blockIdx.x & (BPB - 1)) << 4;
    int base = b * NP;
    pdl_wait();

    const float4* __restrict__ qg = g_Q + base;
    for (int i = tid; i < NP; i += TPB) sQ[i] = __ldg(qg + i);

    float4 p = g_P[base + r0 + rloc];
    float ax = -2.f*p.x, ay = -2.f*p.y, az = -2.f*p.z, aw = p.w;
    const float4* q = sQ + half * HC;
    const float2* __restrict__ W = g_W + base + half * HC;
    __syncthreads();

    float sum = 0.0f;
    for (int m0 = 0; m0 < HC; m0 += 32) {
        int m = m0 + sub;
        float4 qa = q[m], qb = q[m + 8];
        float4 qc = q[m + 16], qd = q[m + 24];
        float da = fmaf(ax,qa.x, fmaf(ay,qa.y, fmaf(az,qa.z, qa.w + aw)));
        float db = fmaf(ax,qb.x, fmaf(ay,qb.y, fmaf(az,qb.z, qb.w + aw)));
        float dc = fmaf(ax,qc.x, fmaf(ay,qc.y, fmaf(az,qc.z, qc.w + aw)));
        float dd = fmaf(ax,qd.x, fmaf(ay,qd.y, fmaf(az,qd.z, qd.w + aw)));
        float ta = c*da, tb = c*db, tc = c*dc, td = c*dd;
        float tm = fmaxf(fmaxf(ta, tb), fmaxf(tc, td));
        if (__any_sync(FULL, tm > SKIP_T)) {
            float2 wa = __ldg(W + m),      wb = __ldg(W + m + 8);
            float2 wc = __ldg(W + m + 16), wd = __ldg(W + m + 24);
            sum = fmaf(ex2a(ta), wa.y, sum);
            sum = fmaf(ex2a(tb), wb.y, sum);
            sum = fmaf(ex2a(tc), wc.y, sum);
            sum = fmaf(ex2a(td), wd.y, sum);
        }
    }
    sum = wred8(sum);
    if (sub == 0) sA[rloc][half] = sum;
    __syncthreads();
    if (tid < RPB) {
        int id2 = base + r0 + tid;
        float s = sA[tid][0] + sA[tid][1];
        g_rs[id2] = g_remainL[id2] / (s + 1e-9f);
    }
}

// ---- Pass B: column sums -> colscale; writes g_W = {rcR, remainR'} ----
template <bool V>
__global__ __launch_bounds__(TPB) void emd_passB(float c) {
    __shared__ float4 sQ[NP];
    __shared__ float sB[RPB][2];
    int tid = threadIdx.x, lane = tid & 31, w = tid >> 5;
    int half = w & 1, sub = lane & 7;
    int rloc = ((w >> 1) << 2) + (lane >> 3);
    int b = blockIdx.x >> 7;
    int r0 = (blockIdx.x & (BPB - 1)) << 4;
    int base = b * NP;
    pdl_wait();

    const float4* __restrict__ qg = g_P + base;
    for (int i = tid; i < NP; i += TPB) sQ[i] = __ldg(qg + i);

    float4 p = g_Q[base + r0 + rloc];             // column point (set 2)
    float ax = -2.f*p.x, ay = -2.f*p.y, az = -2.f*p.z, aw = p.w;
    const float4* q = sQ + half * HC;
    const float*  __restrict__ rs = g_rs + base + half * HC;
    __syncthreads();

    float sum = 0.0f;
    for (int n0 = 0; n0 < HC; n0 += 32) {
        int n = n0 + sub;
        float4 qa = q[n], qb = q[n + 8];
        float4 qc = q[n + 16], qd = q[n + 24];
        float da = fmaf(ax,qa.x, fmaf(ay,qa.y, fmaf(az,qa.z, qa.w + aw)));
        float db = fmaf(ax,qb.x, fmaf(ay,qb.y, fmaf(az,qb.z, qb.w + aw)));
        float dc = fmaf(ax,qc.x, fmaf(ay,qc.y, fmaf(az,qc.z, qc.w + aw)));
        float dd = fmaf(ax,qd.x, fmaf(ay,qd.y, fmaf(az,qd.z, qd.w + aw)));
        float ta = c*da, tb = c*db, tc = c*dc, td = c*dd;
        bool act = true;
        if (V) {
            float tm = fmaxf(fmaxf(ta, tb), fmaxf(tc, td));
            act = __any_sync(FULL, tm > SKIP_T);
        }
        if (act) {
            sum = fmaf(ex2a(ta), __ldg(rs + n),      sum);
            sum = fmaf(ex2a(tb), __ldg(rs + n + 8),  sum);
            sum = fmaf(ex2a(tc), __ldg(rs + n + 16), sum);
            sum = fmaf(ex2a(td), __ldg(rs + n + 24), sum);
        }
    }
    sum = wred8(sum);
    if (sub == 0) sB[rloc][half] = sum;
    __syncthreads();
    if (tid < RPB) {
        int id2 = base + r0 + tid;
        float s = sB[tid][0] + sB[tid][1];
        float remR = g_W[id2].y;
        float ss = fmaf(remR, s, 1e-9f);
        float cs = fminf(remR / ss, 1.0f);
        float colW = cs * (remR * s);
        g_W[id2] = make_float2(remR * cs, fmaxf(remR - colW, 0.0f));
    }
}

// ---- Fused CA: cost+remainL of level i (c1), rowsum of level i+1 (c2) ----
// MODE 0: c1 == 4*c2 < 0 : e2 = ex2(c2*d2), e1 = e2^4       (levels 0..7)
// MODE 1: c2 == 0 (i==8) : z = sum(remainR), one exp for c1
// MODE 2: c1 == 0 (i==9) : exp == 1, no next level
template <int MODE, bool V2, bool V1>
__global__ __launch_bounds__(TPB) void emd_passCA(float c1, float c2) {
    __shared__ float4 sQ[NP];
    __shared__ float sU[RPB][2], sC[RPB][2], sZ[RPB][2];
    int tid = threadIdx.x, lane = tid & 31, w = tid >> 5;
    int half = w & 1, sub = lane & 7;
    int rloc = ((w >> 1) << 2) + (lane >> 3);
    int b = blockIdx.x >> 7;
    int r0 = (blockIdx.x & (BPB - 1)) << 4;
    int base = b * NP;
    pdl_wait();

    const float4* __restrict__ qg = g_Q + base;
    for (int i = tid; i < NP; i += TPB) sQ[i] = __ldg(qg + i);

    float4 p = g_P[base + r0 + rloc];
    float ax = -2.f*p.x, ay = -2.f*p.y, az = -2.f*p.z, aw = p.w;
    const float4* q = sQ + half * HC;
    const float2* __restrict__ W = g_W + base + half * HC;
    __syncthreads();

    float usum = 0.f, csum = 0.f, z = 0.f;
    for (int m0 = 0; m0 < HC; m0 += 32) {
        int m = m0 + sub;
        float4 qa = q[m], qb = q[m + 8];
        float4 qc = q[m + 16], qd = q[m + 24];
        float da = fmaf(ax,qa.x, fmaf(ay,qa.y, fmaf(az,qa.z, qa.w + aw)));
        float db = fmaf(ax,qb.x, fmaf(ay,qb.y, fmaf(az,qb.z, qb.w + aw)));
        float dc = fmaf(ax,qc.x, fmaf(ay,qc.y, fmaf(az,qc.z, qc.w + aw)));
        float dd = fmaf(ax,qd.x, fmaf(ay,qd.y, fmaf(az,qd.z, qd.w + aw)));

        if (MODE == 0) {
            float ta = c2*da, tb = c2*db, tc = c2*dc, td = c2*dd;
            float tm = fmaxf(fmaxf(ta, tb), fmaxf(tc, td));
            bool act2 = true;
            if (V2) act2 = __any_sync(FULL, tm > SKIP_T);
            if (act2) {
                float2 wa = __ldg(W + m),      wb = __ldg(W + m + 8);
                float2 wc = __ldg(W + m + 16), wd = __ldg(W + m + 24);
                float ea = ex2a(ta), eb = ex2a(tb);
                float ec = ex2a(tc), ed = ex2a(td);
                z = fmaf(ea, wa.y, z);
                z = fmaf(eb, wb.y, z);
                z = fmaf(ec, wc.y, z);
                z = fmaf(ed, wd.y, z);
                bool act1 = true;
                if (V1) act1 = __any_sync(FULL, tm > SKIP4_T);
                if (act1) {
                    float sa = ea*ea, sb = eb*eb, sc2 = ec*ec, sd = ed*ed;
                    float ua = (sa*sa)*wa.x, ub = (sb*sb)*wb.x;
                    float uc = (sc2*sc2)*wc.x, ud = (sd*sd)*wd.x;
                    usum += (ua + ub) + (uc + ud);
                    csum = fmaf(ua, sqrta(fmaxf(da, 0.f)), csum);
                    csum = fmaf(ub, sqrta(fmaxf(db, 0.f)), csum);
                    csum = fmaf(uc, sqrta(fmaxf(dc, 0.f)), csum);
                    csum = fmaf(ud, sqrta(fmaxf(dd, 0.f)), csum);
                }
            }
        } else {
            float2 wa = __ldg(W + m),      wb = __ldg(W + m + 8);
            float2 wc = __ldg(W + m + 16), wd = __ldg(W + m + 24);
            if (MODE == 1) {
                z += (wa.y + wb.y) + (wc.y + wd.y);
                float ua = ex2a(c1*da)*wa.x, ub = ex2a(c1*db)*wb.x;
                float uc = ex2a(c1*dc)*wc.x, ud = ex2a(c1*dd)*wd.x;
                usum += (ua + ub) + (uc + ud);
                csum = fmaf(ua, sqrta(fmaxf(da, 0.f)), csum);
                csum = fmaf(ub, sqrta(fmaxf(db, 0.f)), csum);
                csum = fmaf(uc, sqrta(fmaxf(dc, 0.f)), csum);
                csum = fmaf(ud, sqrta(fmaxf(dd, 0.f)), csum);
            } else {                               // MODE 2: exp == 1
                usum += (wa.x + wb.x) + (wc.x + wd.x);
                csum = fmaf(wa.x, sqrta(fmaxf(da, 0.f)), csum);
                csum = fmaf(wb.x, sqrta(fmaxf(db, 0.f)), csum);
                csum = fmaf(wc.x, sqrta(fmaxf(dc, 0.f)), csum);
                csum = fmaf(wd.x, sqrta(fmaxf(dd, 0.f)), csum);
            }
        }
    }
    usum = wred8(usum);
    csum = wred8(csum);
    if (MODE < 2) z = wred8(z);

    if (sub == 0) {
        sU[rloc][half] = usum;
        sC[rloc][half] = csum;
        sZ[rloc][half] = (MODE < 2) ? z : 0.f;
    }
    __syncthreads();
    if (tid < RPB) {
        int id2 = base + r0 + tid;
        float rsc = g_rs[id2];
        float u = sU[tid][0] + sU[tid][1];
        float cv = sC[tid][0] + sC[tid][1];
        float newL = fmaxf(g_remainL[id2] - rsc * u, 0.0f);
        g_remainL[id2] = newL;
        if (MODE < 2)
            g_rs[id2] = newL / (sZ[tid][0] + sZ[tid][1] + 1e-9f);
        float costv = rsc * cv;
        costv += __shfl_xor_sync(0xFFFFu, costv, 1);
        costv += __shfl_xor_sync(0xFFFFu, costv, 2);
        costv += __shfl_xor_sync(0xFFFFu, costv, 4);
        costv += __shfl_xor_sync(0xFFFFu, costv, 8);
        if (tid == 0) atomicAdd(&g_cost[b], costv);
    }
}

__global__ void emd_final(float* __restrict__ out) {
    pdl_wait();
    int i = threadIdx.x;
    if (i < NB) out[i] = g_cost[i];
}

// ---- PDL launch helper ----
template <typename K, typename... Args>
static void pdl_launch(K kern, dim3 grid, dim3 block, Args... args) {
    cudaLaunchConfig_t cfg = {};
    cfg.gridDim = grid;
    cfg.blockDim = block;
    cfg.dynamicSmemBytes = 0;
    cfg.stream = 0;
    cudaLaunchAttribute attr[1];
    attr[0].id = cudaLaunchAttributeProgrammaticStreamSerialization;
    attr[0].val.programmaticStreamSerializationAllowed = 1;
    cfg.attrs = attr;
    cfg.numAttrs = 1;
    cudaLaunchKernelEx(&cfg, kern, args...);
}

extern "C" void kernel_launch(void* const* d_in, const int* in_sizes, int n_in,
                              void* d_out, int out_size) {
    const float* x1 = (const float*)d_in[0];
    const float* x2 = (const float*)d_in[1];
    float* out = (float*)d_out;

    pdl_launch(emd_init, dim3((NB * NP + 255) / 256), dim3(256), x1, x2);

    // levels j = 7..0 -> -4^j ; j=-1 -> -0.25 ; j=-2 -> 0
    const float levels[10] = {-16384.f, -4096.f, -1024.f, -256.f, -64.f,
                              -16.f, -4.f, -1.f, -0.25f, 0.f};
    const float L2E = 1.4426950408889634f;

    pdl_launch(emd_passA, dim3(GRID), dim3(TPB), levels[0] * L2E);
    for (int i = 0; i < 10; i++) {
        float c1 = levels[i] * L2E;
        float c2 = (i < 9) ? levels[i + 1] * L2E : 0.0f;

        if (i < 4) pdl_launch(emd_passB<true >, dim3(GRID), dim3(TPB), c1);
        else       pdl_launch(emd_passB<false>, dim3(GRID), dim3(TPB), c1);

        if (i <= 2)      pdl_launch(emd_passCA<0, true,  true >, dim3(GRID), dim3(TPB), c1, c2);
        else if (i == 3) pdl_launch(emd_passCA<0, false, true >, dim3(GRID), dim3(TPB), c1, c2);
        else if (i <= 7) pdl_launch(emd_passCA<0, false, false>, dim3(GRID), dim3(TPB), c1, c2);
        else if (i == 8) pdl_launch(emd_passCA<1, false, false>, dim3(GRID), dim3(TPB), c1, 0.f);
        else             pdl_launch(emd_passCA<2, false, false>, dim3(GRID), dim3(TPB), 0.f, 0.f);
    }
    pdl_launch(emd_final, dim3(1), dim3(32), out);
}

// round 16
// speedup vs baseline: 1.1048x; 1.1048x over previous
#include <cuda_runtime.h>

// EarthMoverDistance auction (B=8, N=M=2048).
// Round-14 proven base (SPLIT=8, warp-pair column halves, linear d2, float2
// payload, power trick, PDL) + coefficient folding (t = c*d2 directly from 4
// FMAs; sqrt recovered via post-scale K=1/sqrt(-c)), level-9 B sweep replaced
// by an O(N) reduction, level-8 z-sum precomputed.

#define NB 8
#define NP 2048
#define TPB 256
#define RPB 16                   // rows per block
#define BPB (NP / RPB)           // 128 blocks per batch
#define GRID (NB * BPB)          // 1024 blocks
#define HC (NP / 2)              // columns per warp (half range)
#define FULL 0xFFFFFFFFu
#define SKIP_T  (-125.0f)
#define SKIP4_T (-31.25f)

// Static scratch (no allocations)
__device__ float4 g_P[NB * NP];      // set1 {x,y,z,|p|^2}
__device__ float4 g_Q[NB * NP];      // set2 {x,y,z,|q|^2}
__device__ float2 g_W[NB * NP];      // {rcR, remainR}
__device__ float  g_rs[NB * NP];     // rowscale
__device__ float  g_remainL[NB * NP];
__device__ float  g_sumR[NB];
__device__ float  g_cost[NB];

__device__ __forceinline__ float ex2a(float x) {
    float r; asm("ex2.approx.f32 %0, %1;" : "=f"(r) : "f"(x)); return r;
}
__device__ __forceinline__ float sqrta(float x) {
    float r; asm("sqrt.approx.f32 %0, %1;" : "=f"(r) : "f"(x)); return r;
}
__device__ __forceinline__ float wred8(float v) {
    v += __shfl_xor_sync(FULL, v, 1);
    v += __shfl_xor_sync(FULL, v, 2);
    v += __shfl_xor_sync(FULL, v, 4);
    return v;
}
__device__ __forceinline__ void pdl_wait() {
    cudaGridDependencySynchronize();
}

__global__ void emd_init(const float* __restrict__ x1,
                         const float* __restrict__ x2) {
    int i = blockIdx.x * blockDim.x + threadIdx.x;
    pdl_wait();
    if (i < NB) g_cost[i] = 0.0f;
    if (i < NB * NP) {
        float a = x1[3*i], b = x1[3*i+1], c = x1[3*i+2];
        g_P[i] = make_float4(a, b, c, fmaf(a, a, fmaf(b, b, c * c)));
        float d = x2[3*i], e = x2[3*i+1], f = x2[3*i+2];
        g_Q[i] = make_float4(d, e, f, fmaf(d, d, fmaf(e, e, f * f)));
        g_W[i] = make_float2(0.0f, 1.0f);   // {rcR, remainR=multiR}
        g_rs[i] = 0.0f;
        g_remainL[i] = 1.0f;                // multiL
    }
}

// ---- Pass A (level 0 only): rowscale = remainL / (rowsum + 1e-9) ----
// Coefs folded with c: t = c*d2 produced by 4 FMAs.
__global__ __launch_bounds__(TPB) void emd_passA(float c) {
    __shared__ float sA[RPB][2];
    int tid = threadIdx.x, lane = tid & 31, w = tid >> 5;
    int half = w & 1, sub = lane & 7;
    int rloc = ((w >> 1) << 2) + (lane >> 3);     // 0..15
    int b = blockIdx.x >> 7;
    int r0 = (blockIdx.x & (BPB - 1)) << 4;
    int base = b * NP;
    pdl_wait();

    float4 p = g_P[base + r0 + rloc];
    float cm2 = -2.f * c;
    float ax = cm2*p.x, ay = cm2*p.y, az = cm2*p.z, aw = c*p.w;
    const float4* __restrict__ q = g_Q + base + half * HC;
    const float2* __restrict__ W = g_W + base + half * HC;

    float sum = 0.0f;
    for (int m0 = 0; m0 < HC; m0 += 32) {
        int m = m0 + sub;
        float4 qa = __ldg(q + m), qb = __ldg(q + m + 8);
        float4 qc = __ldg(q + m + 16), qd = __ldg(q + m + 24);
        float ta = fmaf(ax,qa.x, fmaf(ay,qa.y, fmaf(az,qa.z, fmaf(c,qa.w, aw))));
        float tb = fmaf(ax,qb.x, fmaf(ay,qb.y, fmaf(az,qb.z, fmaf(c,qb.w, aw))));
        float tc = fmaf(ax,qc.x, fmaf(ay,qc.y, fmaf(az,qc.z, fmaf(c,qc.w, aw))));
        float td = fmaf(ax,qd.x, fmaf(ay,qd.y, fmaf(az,qd.z, fmaf(c,qd.w, aw))));
        float tm = fmaxf(fmaxf(ta, tb), fmaxf(tc, td));
        if (__any_sync(FULL, tm > SKIP_T)) {
            float2 wa = __ldg(W + m),      wb = __ldg(W + m + 8);
            float2 wc = __ldg(W + m + 16), wd = __ldg(W + m + 24);
            sum = fmaf(ex2a(ta), wa.y, sum);
            sum = fmaf(ex2a(tb), wb.y, sum);
            sum = fmaf(ex2a(tc), wc.y, sum);
            sum = fmaf(ex2a(td), wd.y, sum);
        }
    }
    sum = wred8(sum);
    if (sub == 0) sA[rloc][half] = sum;
    __syncthreads();
    if (tid < RPB) {
        int id2 = base + r0 + tid;
        float s = sA[tid][0] + sA[tid][1];
        g_rs[id2] = g_remainL[id2] / (s + 1e-9f);
    }
}

// ---- Pass B: column sums -> colscale; writes g_W = {rcR, remainR'} ----
template <bool V>
__global__ __launch_bounds__(TPB) void emd_passB(float c) {
    __shared__ float sB[RPB][2];
    int tid = threadIdx.x, lane = tid & 31, w = tid >> 5;
    int half = w & 1, sub = lane & 7;
    int rloc = ((w >> 1) << 2) + (lane >> 3);
    int b = blockIdx.x >> 7;
    int r0 = (blockIdx.x & (BPB - 1)) << 4;
    int base = b * NP;
    pdl_wait();

    float4 p = g_Q[base + r0 + rloc];             // column point (set 2)
    float cm2 = -2.f * c;
    float ax = cm2*p.x, ay = cm2*p.y, az = cm2*p.z, aw = c*p.w;
    const float4* __restrict__ q  = g_P  + base + half * HC;
    const float*  __restrict__ rs = g_rs + base + half * HC;

    float sum = 0.0f;
    for (int n0 = 0; n0 < HC; n0 += 32) {
        int n = n0 + sub;
        float4 qa = __ldg(q + n), qb = __ldg(q + n + 8);
        float4 qc = __ldg(q + n + 16), qd = __ldg(q + n + 24);
        float ta = fmaf(ax,qa.x, fmaf(ay,qa.y, fmaf(az,qa.z, fmaf(c,qa.w, aw))));
        float tb = fmaf(ax,qb.x, fmaf(ay,qb.y, fmaf(az,qb.z, fmaf(c,qb.w, aw))));
        float tc = fmaf(ax,qc.x, fmaf(ay,qc.y, fmaf(az,qc.z, fmaf(c,qc.w, aw))));
        float td = fmaf(ax,qd.x, fmaf(ay,qd.y, fmaf(az,qd.z, fmaf(c,qd.w, aw))));
        bool act = true;
        if (V) {
            float tm = fmaxf(fmaxf(ta, tb), fmaxf(tc, td));
            act = __any_sync(FULL, tm > SKIP_T);
        }
        if (act) {
            sum = fmaf(ex2a(ta), __ldg(rs + n),      sum);
            sum = fmaf(ex2a(tb), __ldg(rs + n + 8),  sum);
            sum = fmaf(ex2a(tc), __ldg(rs + n + 16), sum);
            sum = fmaf(ex2a(td), __ldg(rs + n + 24), sum);
        }
    }
    sum = wred8(sum);
    if (sub == 0) sB[rloc][half] = sum;
    __syncthreads();
    if (tid < RPB) {
        int id2 = base + r0 + tid;
        float s = sB[tid][0] + sB[tid][1];
        float remR = g_W[id2].y;
        float ss = fmaf(remR, s, 1e-9f);
        float cs = fminf(remR / ss, 1.0f);
        float colW = cs * (remR * s);
        g_W[id2] = make_float2(remR * cs, fmaxf(remR - colW, 0.0f));
    }
}

// ---- Mini: g_sumR[b] = sum_m remainR (after B_8) ----
__global__ void emd_sumR() {
    __shared__ float sm[8];
    int b = blockIdx.x, tid = threadIdx.x;
    pdl_wait();
    const float2* __restrict__ W = g_W + b * NP;
    float s = 0.f;
    for (int m = tid; m < NP; m += TPB) s += W[m].y;
    for (int o = 16; o; o >>= 1) s += __shfl_xor_sync(FULL, s, o);
    if ((tid & 31) == 0) sm[tid >> 5] = s;
    __syncthreads();
    if (tid < 8) {
        float v = sm[tid];
        v += __shfl_xor_sync(0xFFu, v, 1);
        v += __shfl_xor_sync(0xFFu, v, 2);
        v += __shfl_xor_sync(0xFFu, v, 4);
        if (tid == 0) g_sumR[b] = v;
    }
}

// ---- Mini: replaces pass B at level 9 (c=0 -> colsum = sum_n rowscale) ----
__global__ void emd_colfix() {
    __shared__ float sm[8];
    __shared__ float stot;
    int b = blockIdx.x, tid = threadIdx.x;
    pdl_wait();
    const float* __restrict__ rs = g_rs + b * NP;
    float s = 0.f;
    for (int n = tid; n < NP; n += TPB) s += rs[n];
    for (int o = 16; o; o >>= 1) s += __shfl_xor_sync(FULL, s, o);
    if ((tid & 31) == 0) sm[tid >> 5] = s;
    __syncthreads();
    if (tid < 8) {
        float v = sm[tid];
        v += __shfl_xor_sync(0xFFu, v, 1);
        v += __shfl_xor_sync(0xFFu, v, 2);
        v += __shfl_xor_sync(0xFFu, v, 4);
        if (tid == 0) stot = v;
    }
    __syncthreads();
    float tot = stot;
    float2* W = g_W + b * NP;
    for (int m = tid; m < NP; m += TPB) {
        float remR = W[m].y;
        float ss = fmaf(remR, tot, 1e-9f);
        float cs = fminf(remR / ss, 1.0f);
        float colW = cs * (remR * tot);
        W[m] = make_float2(remR * cs, fmaxf(remR - colW, 0.0f));
    }
}

// ---- Fused CA: cost+remainL of level i, rowsum of level i+1 ----
// MODE 0: cf = c2 (c1 = 4*c2): t = c2*d2 via folded FMAs; e1 = e2^4;
//         sqrt(d2) = sqrt(-t)*K, K = 1/sqrt(-c2).   (levels 0..7)
// MODE 1: cf = c1 (i==8, c2=0): z = g_sumR[b]; sqrt(d2) = sqrt(-t)*K, K=1/sqrt(-c1).
// MODE 2: i==9 (c1=0): exp == 1, raw d2, K unused.
template <int MODE, bool V2, bool V1>
__global__ __launch_bounds__(TPB) void emd_passCA(float cf, float K) {
    __shared__ float sU[RPB][2], sC[RPB][2], sZ[RPB][2];
    int tid = threadIdx.x, lane = tid & 31, w = tid >> 5;
    int half = w & 1, sub = lane & 7;
    int rloc = ((w >> 1) << 2) + (lane >> 3);
    int b = blockIdx.x >> 7;
    int r0 = (blockIdx.x & (BPB - 1)) << 4;
    int base = b * NP;
    pdl_wait();

    float4 p = g_P[base + r0 + rloc];
    // MODE 0/1: coefs folded with cf; MODE 2: raw d2 coefs.
    float cc  = (MODE < 2) ? cf : 1.0f;
    float cm2 = -2.f * cc;
    float ax = cm2*p.x, ay = cm2*p.y, az = cm2*p.z, aw = cc*p.w;
    const float4* __restrict__ q = g_Q + base + half * HC;
    const float2* __restrict__ W = g_W + base + half * HC;

    float usum = 0.f, csum = 0.f, z = 0.f;
    for (int m0 = 0; m0 < HC; m0 += 32) {
        int m = m0 + sub;
        float4 qa = __ldg(q + m), qb = __ldg(q + m + 8);
        float4 qc = __ldg(q + m + 16), qd = __ldg(q + m + 24);
        float ta = fmaf(ax,qa.x, fmaf(ay,qa.y, fmaf(az,qa.z, fmaf(cc,qa.w, aw))));
        float tb = fmaf(ax,qb.x, fmaf(ay,qb.y, fmaf(az,qb.z, fmaf(cc,qb.w, aw))));
        float tc = fmaf(ax,qc.x, fmaf(ay,qc.y, fmaf(az,qc.z, fmaf(cc,qc.w, aw))));
        float td = fmaf(ax,qd.x, fmaf(ay,qd.y, fmaf(az,qd.z, fmaf(cc,qd.w, aw))));

        if (MODE == 0) {
            float tm = fmaxf(fmaxf(ta, tb), fmaxf(tc, td));
            bool act2 = true;
            if (V2) act2 = __any_sync(FULL, tm > SKIP_T);
            if (act2) {
                float2 wa = __ldg(W + m),      wb = __ldg(W + m + 8);
                float2 wc = __ldg(W + m + 16), wd = __ldg(W + m + 24);
                float ea = ex2a(ta), eb = ex2a(tb);
                float ec = ex2a(tc), ed = ex2a(td);
                z = fmaf(ea, wa.y, z);
                z = fmaf(eb, wb.y, z);
                z = fmaf(ec, wc.y, z);
                z = fmaf(ed, wd.y, z);
                bool act1 = true;
                if (V1) act1 = __any_sync(FULL, tm > SKIP4_T);
                if (act1) {
                    float sa = ea*ea, sb = eb*eb, sc2 = ec*ec, sd = ed*ed;
                    float ua = (sa*sa)*wa.x, ub = (sb*sb)*wb.x;
                    float uc = (sc2*sc2)*wc.x, ud = (sd*sd)*wd.x;
                    usum += (ua + ub) + (uc + ud);
                    csum = fmaf(ua, sqrta(fmaxf(-ta, 0.f)), csum);
                    csum = fmaf(ub, sqrta(fmaxf(-tb, 0.f)), csum);
                    csum = fmaf(uc, sqrta(fmaxf(-tc, 0.f)), csum);
                    csum = fmaf(ud, sqrta(fmaxf(-td, 0.f)), csum);
                }
            }
        } else {
            float2 wa = __ldg(W + m),      wb = __ldg(W + m + 8);
            float2 wc = __ldg(W + m + 16), wd = __ldg(W + m + 24);
            if (MODE == 1) {
                float ua = ex2a(ta)*wa.x, ub = ex2a(tb)*wb.x;
                float uc = ex2a(tc)*wc.x, ud = ex2a(td)*wd.x;
                usum += (ua + ub) + (uc + ud);
                csum = fmaf(ua, sqrta(fmaxf(-ta, 0.f)), csum);
                csum = fmaf(ub, sqrta(fmaxf(-tb, 0.f)), csum);
                csum = fmaf(uc, sqrta(fmaxf(-tc, 0.f)), csum);
                csum = fmaf(ud, sqrta(fmaxf(-td, 0.f)), csum);
            } else {                               // MODE 2: exp == 1, t = d2
                usum += (wa.x + wb.x) + (wc.x + wd.x);
                csum = fmaf(wa.x, sqrta(fmaxf(ta, 0.f)), csum);
                csum = fmaf(wb.x, sqrta(fmaxf(tb, 0.f)), csum);
                csum = fmaf(wc.x, sqrta(fmaxf(tc, 0.f)), csum);
                csum = fmaf(wd.x, sqrta(fmaxf(td, 0.f)), csum);
            }
        }
    }
    usum = wred8(usum);
    csum = wred8(csum);
    if (MODE == 0) z = wred8(z);

    if (sub == 0) {
        sU[rloc][half] = usum;
        sC[rloc][half] = csum;
        sZ[rloc][half] = (MODE == 0) ? z : 0.f;
    }
    __syncthreads();
    if (tid < RPB) {
        int id2 = base + r0 + tid;
        float rsc = g_rs[id2];
        float u = sU[tid][0] + sU[tid][1];
        float cv = (sC[tid][0] + sC[tid][1]) * ((MODE < 2) ? K : 1.0f);
        float newL = fmaxf(g_remainL[id2] - rsc * u, 0.0f);
        g_remainL[id2] = newL;
        if (MODE == 0)
            g_rs[id2] = newL / (sZ[tid][0] + sZ[tid][1] + 1e-9f);
        else if (MODE == 1)
            g_rs[id2] = newL / (g_sumR[b] + 1e-9f);
        float costv = rsc * cv;
        costv += __shfl_xor_sync(0xFFFFu, costv, 1);
        costv += __shfl_xor_sync(0xFFFFu, costv, 2);
        costv += __shfl_xor_sync(0xFFFFu, costv, 4);
        costv += __shfl_xor_sync(0xFFFFu, costv, 8);
        if (tid == 0) atomicAdd(&g_cost[b], costv);
    }
}

__global__ void emd_final(float* __restrict__ out) {
    pdl_wait();
    int i = threadIdx.x;
    if (i < NB) out[i] = g_cost[i];
}

// ---- PDL launch helper ----
template <typename K, typename... Args>
static void pdl_launch(K kern, dim3 grid, dim3 block, Args... args) {
    cudaLaunchConfig_t cfg = {};
    cfg.gridDim = grid;
    cfg.blockDim = block;
    cfg.dynamicSmemBytes = 0;
    cfg.stream = 0;
    cudaLaunchAttribute attr[1];
    attr[0].id = cudaLaunchAttributeProgrammaticStreamSerialization;
    attr[0].val.programmaticStreamSerializationAllowed = 1;
    cfg.attrs = attr;
    cfg.numAttrs = 1;
    cudaLaunchKernelEx(&cfg, kern, args...);
}

extern "C" void kernel_launch(void* const* d_in, const int* in_sizes, int n_in,
                              void* d_out, int out_size) {
    const float* x1 = (const float*)d_in[0];
    const float* x2 = (const float*)d_in[1];
    float* out = (float*)d_out;

    pdl_launch(emd_init, dim3((NB * NP + 255) / 256), dim3(256), x1, x2);

    // levels j = 7..0 -> -4^j ; j=-1 -> -0.25 ; j=-2 -> 0
    const float levels[10] = {-16384.f, -4096.f, -1024.f, -256.f, -64.f,
                              -16.f, -4.f, -1.f, -0.25f, 0.f};
    const float L2E = 1.4426950408889634f;

    pdl_launch(emd_passA, dim3(GRID), dim3(TPB), levels[0] * L2E);
    for (int i = 0; i < 10; i++) {
        float c1 = levels[i] * L2E;

        if (i < 9) {
            if (i < 4) pdl_launch(emd_passB<true >, dim3(GRID), dim3(TPB), c1);
            else       pdl_launch(emd_passB<false>, dim3(GRID), dim3(TPB), c1);
        } else {
            pdl_launch(emd_colfix, dim3(NB), dim3(TPB));   // level 9: c=0
        }

        if (i < 8) {
            float c2 = levels[i + 1] * L2E;
            float K2 = 1.0f / sqrtf(-c2);
            if (i <= 2)      pdl_launch(emd_passCA<0, true,  true >, dim3(GRID), dim3(TPB), c2, K2);
            else if (i == 3) pdl_launch(emd_passCA<0, false, true >, dim3(GRID), dim3(TPB), c2, K2);
            else             pdl_launch(emd_passCA<0, false, false>, dim3(GRID), dim3(TPB), c2, K2);
        } else if (i == 8) {
            pdl_launch(emd_sumR, dim3(NB), dim3(TPB));     // sum remainR after B_8
            float K1 = 1.0f / sqrtf(-c1);
            pdl_launch(emd_passCA<1, false, false>, dim3(GRID), dim3(TPB), c1, K1);
        } else {
            pdl_launch(emd_passCA<2, false, false>, dim3(GRID), dim3(TPB), 0.f, 1.0f);
        }
    }
    pdl_launch(emd_final, dim3(1), dim3(32), out);
}

// round 17
// speedup vs baseline: 1.3420x; 1.2147x over previous
#include <cuda_runtime.h>

// EarthMoverDistance auction (B=8, N=M=2048).
// Register-replication layout: each lane owns ONE distinct column (coalesced,
// no lane-duplicated loads) and carries FOUR rows' folded coefficients in
// registers. Per warp-iteration (128 pairs): 1 LDG.128 + 1 LDG.64 = 6 L1
// wavefronts (was 24). Folded t=c*d2, power trick e1=e2^4, exp-free last
// levels, level-9 B replaced by O(N) reduction, PDL everywhere.

#define NB 8
#define NP 2048
#define TPB 256
#define RPB 16                   // rows per block (8 warps x 4 rows / 2 halves)
#define BPB (NP / RPB)           // 128 blocks per batch
#define GRID (NB * BPB)          // 1024 blocks
#define HC (NP / 2)              // columns per warp (half range)
#define FULL 0xFFFFFFFFu
#define SKIP_T  (-125.0f)
#define SKIP4_T (-31.25f)

// Static scratch (no allocations)
__device__ float4 g_P[NB * NP];      // set1 {x,y,z,|p|^2}
__device__ float4 g_Q[NB * NP];      // set2 {x,y,z,|q|^2}
__device__ float2 g_W[NB * NP];      // {rcR, remainR}
__device__ float  g_rs[NB * NP];     // rowscale
__device__ float  g_remainL[NB * NP];
__device__ float  g_sumR[NB];
__device__ float  g_cost[NB];

__device__ __forceinline__ float ex2a(float x) {
    float r; asm("ex2.approx.f32 %0, %1;" : "=f"(r) : "f"(x)); return r;
}
__device__ __forceinline__ float sqrta(float x) {
    float r; asm("sqrt.approx.f32 %0, %1;" : "=f"(r) : "f"(x)); return r;
}
__device__ __forceinline__ float wred32(float v) {
    v += __shfl_xor_sync(FULL, v, 16);
    v += __shfl_xor_sync(FULL, v, 8);
    v += __shfl_xor_sync(FULL, v, 4);
    v += __shfl_xor_sync(FULL, v, 2);
    v += __shfl_xor_sync(FULL, v, 1);
    return v;
}
__device__ __forceinline__ void pdl_wait() {
    cudaGridDependencySynchronize();
}

__global__ void emd_init(const float* __restrict__ x1,
                         const float* __restrict__ x2) {
    int i = blockIdx.x * blockDim.x + threadIdx.x;
    pdl_wait();
    if (i < NB) g_cost[i] = 0.0f;
    if (i < NB * NP) {
        float a = x1[3*i], b = x1[3*i+1], c = x1[3*i+2];
        g_P[i] = make_float4(a, b, c, fmaf(a, a, fmaf(b, b, c * c)));
        float d = x2[3*i], e = x2[3*i+1], f = x2[3*i+2];
        g_Q[i] = make_float4(d, e, f, fmaf(d, d, fmaf(e, e, f * f)));
        g_W[i] = make_float2(0.0f, 1.0f);   // {rcR, remainR=multiR}
        g_rs[i] = 0.0f;
        g_remainL[i] = 1.0f;                // multiL
    }
}

// ---- Pass A (level 0 only): rowscale = remainL / (rowsum + 1e-9) ----
__global__ __launch_bounds__(TPB) void emd_passA(float c) {
    __shared__ float sA[RPB][2];
    int tid = threadIdx.x, lane = tid & 31, w = tid >> 5;
    int half = w & 1, rgrp = w >> 1;              // 0..3 -> rows rgrp*4..+3
    int b = blockIdx.x >> 7;
    int r0 = (blockIdx.x & (BPB - 1)) << 4;
    int base = b * NP;
    int ridx = base + r0 + rgrp * 4;
    pdl_wait();

    float cm2 = -2.f * c;
    float ax[4], ay[4], az[4], aw[4];
    #pragma unroll
    for (int j = 0; j < 4; j++) {
        float4 p = g_P[ridx + j];
        ax[j] = cm2*p.x; ay[j] = cm2*p.y; az[j] = cm2*p.z; aw[j] = c*p.w;
    }
    const float4* __restrict__ q = g_Q + base + half * HC;
    const float2* __restrict__ W = g_W + base + half * HC;

    float sum[4] = {0.f, 0.f, 0.f, 0.f};
    for (int m0 = 0; m0 < HC; m0 += 32) {
        int m = m0 + lane;
        float4 qv = __ldg(q + m);
        float cw = c * qv.w;
        float t[4];
        #pragma unroll
        for (int j = 0; j < 4; j++)
            t[j] = fmaf(ax[j],qv.x, fmaf(ay[j],qv.y, fmaf(az[j],qv.z, cw + aw[j])));
        float tm = fmaxf(fmaxf(t[0], t[1]), fmaxf(t[2], t[3]));
        if (__any_sync(FULL, tm > SKIP_T)) {
            float2 wv = __ldg(W + m);
            #pragma unroll
            for (int j = 0; j < 4; j++)
                sum[j] = fmaf(ex2a(t[j]), wv.y, sum[j]);
        }
    }
    #pragma unroll
    for (int j = 0; j < 4; j++) sum[j] = wred32(sum[j]);
    if (lane == 0) {
        #pragma unroll
        for (int j = 0; j < 4; j++) sA[rgrp * 4 + j][half] = sum[j];
    }
    __syncthreads();
    if (tid < RPB) {
        int id2 = base + r0 + tid;
        float s = sA[tid][0] + sA[tid][1];
        g_rs[id2] = g_remainL[id2] / (s + 1e-9f);
    }
}

// ---- Pass B: column sums -> colscale; writes g_W = {rcR, remainR'} ----
template <bool V>
__global__ __launch_bounds__(TPB) void emd_passB(float c) {
    __shared__ float sB[RPB][2];
    int tid = threadIdx.x, lane = tid & 31, w = tid >> 5;
    int half = w & 1, rgrp = w >> 1;
    int b = blockIdx.x >> 7;
    int r0 = (blockIdx.x & (BPB - 1)) << 4;
    int base = b * NP;
    int ridx = base + r0 + rgrp * 4;
    pdl_wait();

    float cm2 = -2.f * c;
    float ax[4], ay[4], az[4], aw[4];
    #pragma unroll
    for (int j = 0; j < 4; j++) {
        float4 p = g_Q[ridx + j];                 // column points (set 2)
        ax[j] = cm2*p.x; ay[j] = cm2*p.y; az[j] = cm2*p.z; aw[j] = c*p.w;
    }
    const float4* __restrict__ q  = g_P  + base + half * HC;
    const float*  __restrict__ rs = g_rs + base + half * HC;

    float sum[4] = {0.f, 0.f, 0.f, 0.f};
    for (int n0 = 0; n0 < HC; n0 += 32) {
        int n = n0 + lane;
        float4 qv = __ldg(q + n);
        float cw = c * qv.w;
        float t[4];
        #pragma unroll
        for (int j = 0; j < 4; j++)
            t[j] = fmaf(ax[j],qv.x, fmaf(ay[j],qv.y, fmaf(az[j],qv.z, cw + aw[j])));
        bool act = true;
        if (V) {
            float tm = fmaxf(fmaxf(t[0], t[1]), fmaxf(t[2], t[3]));
            act = __any_sync(FULL, tm > SKIP_T);
        }
        if (act) {
            float rv = __ldg(rs + n);
            #pragma unroll
            for (int j = 0; j < 4; j++)
                sum[j] = fmaf(ex2a(t[j]), rv, sum[j]);
        }
    }
    #pragma unroll
    for (int j = 0; j < 4; j++) sum[j] = wred32(sum[j]);
    if (lane == 0) {
        #pragma unroll
        for (int j = 0; j < 4; j++) sB[rgrp * 4 + j][half] = sum[j];
    }
    __syncthreads();
    if (tid < RPB) {
        int id2 = base + r0 + tid;
        float s = sB[tid][0] + sB[tid][1];
        float remR = g_W[id2].y;
        float ss = fmaf(remR, s, 1e-9f);
        float cs = fminf(remR / ss, 1.0f);
        float colW = cs * (remR * s);
        g_W[id2] = make_float2(remR * cs, fmaxf(remR - colW, 0.0f));
    }
}

// ---- Mini: g_sumR[b] = sum_m remainR (after B_8) ----
__global__ void emd_sumR() {
    __shared__ float sm[8];
    int b = blockIdx.x, tid = threadIdx.x;
    pdl_wait();
    const float2* __restrict__ W = g_W + b * NP;
    float s = 0.f;
    for (int m = tid; m < NP; m += TPB) s += W[m].y;
    for (int o = 16; o; o >>= 1) s += __shfl_xor_sync(FULL, s, o);
    if ((tid & 31) == 0) sm[tid >> 5] = s;
    __syncthreads();
    if (tid < 8) {
        float v = sm[tid];
        v += __shfl_xor_sync(0xFFu, v, 1);
        v += __shfl_xor_sync(0xFFu, v, 2);
        v += __shfl_xor_sync(0xFFu, v, 4);
        if (tid == 0) g_sumR[b] = v;
    }
}

// ---- Mini: replaces pass B at level 9 (c=0 -> colsum = sum_n rowscale) ----
__global__ void emd_colfix() {
    __shared__ float sm[8];
    __shared__ float stot;
    int b = blockIdx.x, tid = threadIdx.x;
    pdl_wait();
    const float* __restrict__ rs = g_rs + b * NP;
    float s = 0.f;
    for (int n = tid; n < NP; n += TPB) s += rs[n];
    for (int o = 16; o; o >>= 1) s += __shfl_xor_sync(FULL, s, o);
    if ((tid & 31) == 0) sm[tid >> 5] = s;
    __syncthreads();
    if (tid < 8) {
        float v = sm[tid];
        v += __shfl_xor_sync(0xFFu, v, 1);
        v += __shfl_xor_sync(0xFFu, v, 2);
        v += __shfl_xor_sync(0xFFu, v, 4);
        if (tid == 0) stot = v;
    }
    __syncthreads();
    float tot = stot;
    float2* W = g_W + b * NP;
    for (int m = tid; m < NP; m += TPB) {
        float remR = W[m].y;
        float ss = fmaf(remR, tot, 1e-9f);
        float cs = fminf(remR / ss, 1.0f);
        float colW = cs * (remR * tot);
        W[m] = make_float2(remR * cs, fmaxf(remR - colW, 0.0f));
    }
}

// ---- Fused CA: cost+remainL of level i, rowsum of level i+1 ----
// MODE 0: cf = c2 (c1 = 4*c2): t = c2*d2 folded; e1 = e2^4; sqrt(d2)=sqrt(-t)*K
// MODE 1: cf = c1 (i==8, c2=0): z = g_sumR[b]; sqrt(d2)=sqrt(-t)*K
// MODE 2: i==9 (c1=0): exp == 1, cc=1 so t = d2, K unused
template <int MODE, bool V2, bool V1>
__global__ __launch_bounds__(TPB) void emd_passCA(float cf, float K) {
    __shared__ float sU[RPB][2], sC[RPB][2], sZ[RPB][2];
    int tid = threadIdx.x, lane = tid & 31, w = tid >> 5;
    int half = w & 1, rgrp = w >> 1;
    int b = blockIdx.x >> 7;
    int r0 = (blockIdx.x & (BPB - 1)) << 4;
    int base = b * NP;
    int ridx = base + r0 + rgrp * 4;
    pdl_wait();

    float cc  = (MODE < 2) ? cf : 1.0f;
    float cm2 = -2.f * cc;
    float ax[4], ay[4], az[4], aw[4];
    #pragma unroll
    for (int j = 0; j < 4; j++) {
        float4 p = g_P[ridx + j];
        ax[j] = cm2*p.x; ay[j] = cm2*p.y; az[j] = cm2*p.z; aw[j] = cc*p.w;
    }
    const float4* __restrict__ q = g_Q + base + half * HC;
    const float2* __restrict__ W = g_W + base + half * HC;

    float usum[4] = {0,0,0,0}, csum[4] = {0,0,0,0}, z[4] = {0,0,0,0};
    for (int m0 = 0; m0 < HC; m0 += 32) {
        int m = m0 + lane;
        float4 qv = __ldg(q + m);
        float cw = cc * qv.w;
        float t[4];
        #pragma unroll
        for (int j = 0; j < 4; j++)
            t[j] = fmaf(ax[j],qv.x, fmaf(ay[j],qv.y, fmaf(az[j],qv.z, cw + aw[j])));

        if (MODE == 0) {
            float tm = fmaxf(fmaxf(t[0], t[1]), fmaxf(t[2], t[3]));
            bool act2 = true;
            if (V2) act2 = __any_sync(FULL, tm > SKIP_T);
            if (act2) {
                float2 wv = __ldg(W + m);
                float e[4];
                #pragma unroll
                for (int j = 0; j < 4; j++) {
                    e[j] = ex2a(t[j]);
                    z[j] = fmaf(e[j], wv.y, z[j]);
                }
                bool act1 = true;
                if (V1) act1 = __any_sync(FULL, tm > SKIP4_T);
                if (act1) {
                    #pragma unroll
                    for (int j = 0; j < 4; j++) {
                        float s2 = e[j] * e[j];
                        float u = (s2 * s2) * wv.x;
                        usum[j] += u;
                        csum[j] = fmaf(u, sqrta(fmaxf(-t[j], 0.f)), csum[j]);
                    }
                }
            }
        } else {
            float2 wv = __ldg(W + m);
            if (MODE == 1) {
                #pragma unroll
                for (int j = 0; j < 4; j++) {
                    float u = ex2a(t[j]) * wv.x;
                    usum[j] += u;
                    csum[j] = fmaf(u, sqrta(fmaxf(-t[j], 0.f)), csum[j]);
                }
            } else {                              // MODE 2: exp == 1, t = d2
                #pragma unroll
                for (int j = 0; j < 4; j++) {
                    usum[j] += wv.x;
                    csum[j] = fmaf(wv.x, sqrta(fmaxf(t[j], 0.f)), csum[j]);
                }
            }
        }
    }
    #pragma unroll
    for (int j = 0; j < 4; j++) {
        usum[j] = wred32(usum[j]);
        csum[j] = wred32(csum[j]);
        if (MODE == 0) z[j] = wred32(z[j]);
    }
    if (lane == 0) {
        #pragma unroll
        for (int j = 0; j < 4; j++) {
            sU[rgrp * 4 + j][half] = usum[j];
            sC[rgrp * 4 + j][half] = csum[j];
            sZ[rgrp * 4 + j][half] = (MODE == 0) ? z[j] : 0.f;
        }
    }
    __syncthreads();
    if (tid < RPB) {
        int id2 = base + r0 + tid;
        float rsc = g_rs[id2];
        float u = sU[tid][0] + sU[tid][1];
        float cv = (sC[tid][0] + sC[tid][1]) * ((MODE < 2) ? K : 1.0f);
        float newL = fmaxf(g_remainL[id2] - rsc * u, 0.0f);
        g_remainL[id2] = newL;
        if (MODE == 0)
            g_rs[id2] = newL / (sZ[tid][0] + sZ[tid][1] + 1e-9f);
        else if (MODE == 1)
            g_rs[id2] = newL / (g_sumR[b] + 1e-9f);
        float costv = rsc * cv;
        costv += __shfl_xor_sync(0xFFFFu, costv, 1);
        costv += __shfl_xor_sync(0xFFFFu, costv, 2);
        costv += __shfl_xor_sync(0xFFFFu, costv, 4);
        costv += __shfl_xor_sync(0xFFFFu, costv, 8);
        if (tid == 0) atomicAdd(&g_cost[b], costv);
    }
}

__global__ void emd_final(float* __restrict__ out) {
    pdl_wait();
    int i = threadIdx.x;
    if (i < NB) out[i] = g_cost[i];
}

// ---- PDL launch helper ----
template <typename K, typename... Args>
static void pdl_launch(K kern, dim3 grid, dim3 block, Args... args) {
    cudaLaunchConfig_t cfg = {};
    cfg.gridDim = grid;
    cfg.blockDim = block;
    cfg.dynamicSmemBytes = 0;
    cfg.stream = 0;
    cudaLaunchAttribute attr[1];
    attr[0].id = cudaLaunchAttributeProgrammaticStreamSerialization;
    attr[0].val.programmaticStreamSerializationAllowed = 1;
    cfg.attrs = attr;
    cfg.numAttrs = 1;
    cudaLaunchKernelEx(&cfg, kern, args...);
}

extern "C" void kernel_launch(void* const* d_in, const int* in_sizes, int n_in,
                              void* d_out, int out_size) {
    const float* x1 = (const float*)d_in[0];
    const float* x2 = (const float*)d_in[1];
    float* out = (float*)d_out;

    pdl_launch(emd_init, dim3((NB * NP + 255) / 256), dim3(256), x1, x2);

    // levels j = 7..0 -> -4^j ; j=-1 -> -0.25 ; j=-2 -> 0
    const float levels[10] = {-16384.f, -4096.f, -1024.f, -256.f, -64.f,
                              -16.f, -4.f, -1.f, -0.25f, 0.f};
    const float L2E = 1.4426950408889634f;

    pdl_launch(emd_passA, dim3(GRID), dim3(TPB), levels[0] * L2E);
    for (int i = 0; i < 10; i++) {
        float c1 = levels[i] * L2E;

        if (i < 9) {
            if (i < 4) pdl_launch(emd_passB<true >, dim3(GRID), dim3(TPB), c1);
            else       pdl_launch(emd_passB<false>, dim3(GRID), dim3(TPB), c1);
        } else {
            pdl_launch(emd_colfix, dim3(NB), dim3(TPB));   // level 9: c=0
        }

        if (i < 8) {
            float c2 = levels[i + 1] * L2E;
            float K2 = 1.0f / sqrtf(-c2);
            if (i <= 2)      pdl_launch(emd_passCA<0, true,  true >, dim3(GRID), dim3(TPB), c2, K2);
            else if (i == 3) pdl_launch(emd_passCA<0, false, true >, dim3(GRID), dim3(TPB), c2, K2);
            else             pdl_launch(emd_passCA<0, false, false>, dim3(GRID), dim3(TPB), c2, K2);
        } else if (i == 8) {
            pdl_launch(emd_sumR, dim3(NB), dim3(TPB));     // sum remainR after B_8
            float K1 = 1.0f / sqrtf(-c1);
            pdl_launch(emd_passCA<1, false, false>, dim3(GRID), dim3(TPB), c1, K1);
        } else {
            pdl_launch(emd_passCA<2, false, false>, dim3(GRID), dim3(TPB), 0.f, 1.0f);
        }
    }
    pdl_launch(emd_final, dim3(1), dim3(32), out);
}